// round 16
// baseline (speedup 1.0000x reference)
#include <cuda_runtime.h>
#include <cstdint>
#include <cstddef>

// Problem constants (fixed by the dataset)
#define Bn   8
#define Tn   128
#define Un   64
#define U1n  65          // U+1
#define Vn   1024
// blank = V-1 (last class)

#define DDn  208         // padded diagonal count (max dd=190; prefetch reads to +2*GRP)
#define Wn   66          // padded diagonal width (u: 0..65)
#define GRP  4           // DP prefetch depth (diagonals)
#define BIGWM 1000000

#define LOG2E 1.4426950408889634f
#define LN2   0.6931471805599453f

// DIAGONAL-MAJOR scratch (base-2 log domain):
//   gD_blank[b][dd][u]   = lp2_blank(t,u),  dd = t+u
//   gD_emit [b][dd][u+1] = lp2_emit (t,u),  dd = t+u   (+1 shift so a float2 at
//                          [2l] yields (emit[.,2l-1], emit[.,2l]) per lane)
__device__ __align__(16) float gD_blank[Bn * DDn * Wn];
__device__ __align__(16) float gD_emit [Bn * DDn * Wn];
__device__ int g_frame_done[Tn * Bn];    // rows completed per frame f = t*8+b (done @65)

__device__ __forceinline__ float neg_inf() { return __int_as_float(0xff800000u); }

// Base-2 logaddexp: EX2 + degree-5 Estrin poly for log2(1+y), final FFMA fold.
// P(0)=0 keeps -inf algebra NaN-free (z clamped to -45 handles both--inf NaN).
__device__ __forceinline__ float lae2p(float va, float vb) {
    const float C1 =  1.4419672f;
    const float C2 = -0.7096747f;
    const float C3 =  0.4176170f;
    const float C4 = -0.1962970f;
    const float C5 =  0.0463940f;
    float mx = fmaxf(va, vb);
    float mn = fminf(va, vb);
    float z  = fmaxf(mn - mx, -45.0f);
    float y;
    asm("ex2.approx.ftz.f32 %0, %1;" : "=f"(y) : "f"(z));
    float y2 = y * y;
    float t1 = fmaf(C2, y, C1);
    float t2 = fmaf(C4, y, C3);
    float t3 = fmaf(y2, t2, t1);
    float y4 = y2 * y2;
    float P  = fmaf(y4, C5, t3);
    return fmaf(y, P, mx);
}

// ---------------------------------------------------------------------------
__global__ void init_kernel() {
    int i = blockIdx.x * 256 + threadIdx.x;
    if (i < Tn * Bn) g_frame_done[i] = 0;
}

// ---------------------------------------------------------------------------
// Fused kernel (single stream, graph-friendly).
//  blocks 0..7  : DP per batch (warp0 = wavefront DP, warp1 = frame poller)
//  blocks 8..   : lse producer. Block = up to 8 rows of ONE frame (b,t), rows
//                 u = chunk*8 .. chunk*8+7. After __syncthreads, ONE thread does
//                 ONE gpu-scope fence + relaxed counter add (vs per-row release
//                 in R13 — 32x fewer gpu-scope drains, the suspected killer).
// Frame order f = t*8+b: all batches' frame t produced together -> every DP
// block rides the frame watermark; only ~u_last diagonals run as a tail.
// ---------------------------------------------------------------------------
__global__ void __launch_bounds__(256, 5) fused_kernel(
    const float* __restrict__ logits,
    const int*   __restrict__ targets,
    const int*   __restrict__ logit_lengths,
    const int*   __restrict__ target_lengths,
    float*       __restrict__ out)
{
    // ======================= DP blocks =======================
    if (blockIdx.x < Bn) {
        __shared__ int s_wm;                 // diagonal watermark (BIGWM = all)
        if (threadIdx.x == 0) s_wm = -1;
        __syncthreads();

        int b    = blockIdx.x;
        int wib  = threadIdx.x >> 5;
        int lane = threadIdx.x & 31;
        if (wib >= 2) return;

        int Tl = logit_lengths[b];
        int Ul = target_lengths[b];
        const int t_last = Tl - 1;
        const int u_last = Ul;
        const int d_end  = t_last + u_last;

        if (wib == 1) {
            // ---- poller: frame watermark -> diagonal watermark -------------
            // Frame t done when g_frame_done[t*8+b] == 65. Diag dd ready iff
            // frames 0..min(dd,t_last) done; so s_wm = fw (and BIGWM once
            // fw >= t_last).
            int w = -1;
            while (w < t_last) {
                int t = w + 1 + lane;
                int ok;
                if (t <= t_last) {
                    int c;
                    asm volatile("ld.acquire.gpu.global.b32 %0, [%1];"
                                 : "=r"(c) : "l"(g_frame_done + t * Bn + b) : "memory");
                    ok = (c >= U1n);
                } else ok = 1;
                unsigned bal = __ballot_sync(0xffffffffu, ok);
                int adv = (~bal == 0u) ? 32 : (__ffs(~bal) - 1);
                if (adv > 0) {
                    w += adv;
                    if (lane == 0) {
                        __threadfence_block();
                        *(volatile int*)&s_wm = (w >= t_last) ? BIGWM : w;
                    }
                } else {
                    __nanosleep(256);
                }
            }
            if (lane == 0) {
                __threadfence_block();
                *(volatile int*)&s_wm = BIGWM;
            }
            return;
        }

        // ---------------- DP warp ----------------
        const float NEG = neg_inf();
        const float* dbBase = gD_blank + b * DDn * Wn;
        const float* deBase = gD_emit  + b * DDn * Wn;
        const int src = (lane + 31) & 31;
        const bool l0 = (lane == 0);

        int wm_cache = -1;
        auto wait_wm = [&](int need) {
            if (wm_cache >= need) return;
            int v = *(volatile int*)&s_wm;
            while (v < need) { __nanosleep(128); v = *(volatile int*)&s_wm; }
            wm_cache = v;
            __threadfence_block();
        };

        float2 BA[GRP], EA[GRP];
        float  BU[GRP], EU[GRP];

        // Prologue: diagonals 0..GRP-1 feed iterations d = 1..GRP.
        wait_wm(min(GRP - 1, d_end));
#pragma unroll
        for (int k = 0; k < GRP; k++) {
            const float* pB = dbBase + k * Wn;
            const float* pE = deBase + k * Wn;
            BA[k] = *(const float2*)(pB + 2 * lane);
            EA[k] = *(const float2*)(pE + 2 * lane);
            BU[k] = pB[64];
            EU[k] = pE[64];
        }

        // Diagonal d = 0: only cell (0,0) (lane0 slot0) = 0.
        float p0 = l0 ? 0.0f : NEG;
        float p1 = NEG, p2 = NEG;
        float f0 = NEG, f1 = NEG, f2 = NEG;   // snapshot at d == d_end

        for (int g = 1; g <= d_end; g += GRP) {
            // This group's prefetches touch diagonals up to g+2*GRP-2.
            wait_wm(min(g + 2 * GRP - 2, d_end));
#pragma unroll
            for (int k = 0; k < GRP; k++) {
                int d = g + k;
                float s1 = __shfl_sync(0xffffffffu, p1, src);

                float blk0 = BA[k].x, blk1 = BA[k].y, blk2 = BU[k];
                float emt0 = EA[k].x, emt1 = EA[k].y, emt2 = EU[k];

                // Prefetch diagonal d+GRP-1 (for iteration d+GRP) into slot k.
                {
                    int dd = g + k + GRP - 1;
                    const float* pB = dbBase + dd * Wn;
                    const float* pE = deBase + dd * Wn;
                    BA[k] = *(const float2*)(pB + 2 * lane);
                    EA[k] = *(const float2*)(pE + 2 * lane);
                    BU[k] = pB[64];
                    EU[k] = pE[64];
                }

                float nb0 = l0 ? NEG : s1;   // u=2l: left parent = lane l-1 odd col
                float nb1 = p0;              // u=2l+1: left parent local (prev diag)
                float nb2 = p1;              // u=64: left parent = lane31 slot1

                float q0 = lae2p(p0 + blk0, nb0 + emt0);
                float q1 = lae2p(p1 + blk1, nb1 + emt1);
                float q2 = lae2p(p2 + blk2, nb2 + emt2);

                bool last = (d == d_end);
                f0 = last ? q0 : f0;
                f1 = last ? q1 : f1;
                f2 = last ? q2 : f2;

                p0 = q0; p1 = q1; p2 = q2;
            }
        }

        // Extract alpha[t_last][u_last] from snapshot of diagonal d_end.
        float af;
        if (u_last == 64)    af = __shfl_sync(0xffffffffu, f2, 31);
        else if (u_last & 1) af = __shfl_sync(0xffffffffu, f1, u_last >> 1);
        else                 af = __shfl_sync(0xffffffffu, f0, u_last >> 1);

        float fb = dbBase[d_end * Wn + u_last];   // blank lp2 at (t_last,u_last)
        if (lane == 0) out[b] = -(af + fb) * LN2;
        return;
    }

    // ======================= lse producer blocks =======================
    // Block -> (frame f, chunk): 9 chunks per frame (8 rows each, last has 1).
    int fb    = (int)blockIdx.x - Bn;
    int f     = fb / 9;                  // 0..1023, f = t*8 + b
    int chunk = fb - f * 9;              // 0..8
    int t     = f >> 3;
    int b     = f & 7;
    int u     = chunk * 8 + (int)(threadIdx.x >> 5);
    int lane  = threadIdx.x & 31;

    int Tl = logit_lengths[b];
    int Ul = target_lengths[b];

    bool valid = (u <= Un) && (t < Tl) && (u <= Ul);
    if (valid) {
        size_t rowIdx = (size_t)((b * Tn + t) * U1n + u);
        const float4* row = reinterpret_cast<const float4*>(logits) + rowIdx * (Vn / 4);
        float4 v[8];
#pragma unroll
        for (int jj = 0; jj < 8; jj++) v[jj] = row[jj * 32 + lane];

        float m = v[0].x;
#pragma unroll
        for (int jj = 0; jj < 8; jj++) {
            m = fmaxf(m, v[jj].x); m = fmaxf(m, v[jj].y);
            m = fmaxf(m, v[jj].z); m = fmaxf(m, v[jj].w);
        }
        float s = 0.0f;
#pragma unroll
        for (int jj = 0; jj < 8; jj++) {
            s += __expf(v[jj].x - m); s += __expf(v[jj].y - m);
            s += __expf(v[jj].z - m); s += __expf(v[jj].w - m);
        }

        // blank class = V-1: lives in v[7].w of lane 31.
        float blankv = __shfl_sync(0xffffffffu, v[7].w, 31);

#pragma unroll
        for (int off = 16; off; off >>= 1) {
            float om = __shfl_xor_sync(0xffffffffu, m, off);
            float os = __shfl_xor_sync(0xffffffffu, s, off);
            float nm = fmaxf(m, om);
            s = s * __expf(m - nm) + os * __expf(om - nm);
            m = nm;
        }
        float lse = m + __logf(s);

        if (lane == 0) {
            int dd = t + u;
            gD_blank[(b * DDn + dd) * Wn + u] = (blankv - lse) * LOG2E;
            if (u < Ul) {
                int tgt = targets[b * Un + u];
                gD_emit[(b * DDn + dd) * Wn + (u + 1)] =
                    (logits[rowIdx * Vn + tgt] - lse) * LOG2E;
            }
        }
    }

    // ONE publish per block: bar orders all warps' stores before the fence.
    __syncthreads();
    if (threadIdx.x == 0) {
        int nrows = (chunk == 8) ? 1 : 8;    // rows this block accounts for
        asm volatile("fence.acq_rel.gpu;" ::: "memory");
        asm volatile("red.relaxed.gpu.global.add.u32 [%0], %1;"
                     :: "l"(g_frame_done + f), "r"((unsigned)nrows) : "memory");
    }
}

// ---------------------------------------------------------------------------
extern "C" void kernel_launch(void* const* d_in, const int* in_sizes, int n_in,
                              void* d_out, int out_size)
{
    const float* logits         = (const float*)d_in[0];
    const int*   targets        = (const int*)  d_in[1];
    const int*   logit_lengths  = (const int*)  d_in[2];
    const int*   target_lengths = (const int*)  d_in[3];
    float*       out            = (float*)      d_out;

    int prod_blocks = Tn * Bn * 9;               // 9216 producer blocks
    int blocks      = Bn + prod_blocks;          // DP blocks first (resident early)

    init_kernel<<<(Tn * Bn + 255) / 256, 256>>>();
    fused_kernel<<<blocks, 256>>>(logits, targets, logit_lengths, target_lengths, out);
}

// round 17
// speedup vs baseline: 1.1550x; 1.1550x over previous
#include <cuda_runtime.h>
#include <cstdint>
#include <cstddef>

// Problem constants (fixed by the dataset)
#define Bn   8
#define Tn   128
#define Un   64
#define U1n  65          // U+1
#define Vn   1024
// blank = V-1 (last class)

#define LOG2E 1.4426950408889634f
#define LN2   0.6931471805599453f

// Scratch (BASE-2 log domain). g_blank stored PADDED to stride 66 so the DP
// preload is a flat vectorized copy.
__device__ __align__(16) float g_blank[Bn * Tn * 66];  // lp2[..., blank]
__device__ __align__(16) float g_emit [Bn * Tn * Un];  // lp2[..., targets[b,u]]

__device__ __forceinline__ float neg_inf() { return __int_as_float(0xff800000u); }

// MUFU exp2.
__device__ __forceinline__ float ex2m(float r) {
    float y;
    asm("ex2.approx.ftz.f32 %0, %1;" : "=f"(y) : "f"(r));
    return y;
}

// MUFU-free exp2: magic-constant round-to-int + deg-4 Taylor on f in [-0.5,0.5]
// + exponent insertion by integer add. Valid for r in (-2^22, 2^22); here
// r in [-90, ~0]. 7 fma-pipe ops + 2 alu ops, zero MUFU. Rel err ~4e-5.
__device__ __forceinline__ float ex2p(float r) {
    const float MAGIC = 12582912.0f;       // 1.5 * 2^23
    const float C1 = 0.693147182f;
    const float C2 = 0.240226512f;
    const float C3 = 0.055504109f;
    const float C4 = 0.009618130f;
    float t = r + MAGIC;                   // mantissa now holds rint(r)
    float k = t - MAGIC;                   // k = rint(r)
    float f = r - k;                       // f in [-0.5, 0.5]
    float p = fmaf(fmaf(fmaf(fmaf(C4, f, C3), f, C2), f, C1), f, 1.0f);  // 2^f
    // t_bits = 0x4B400000 + k (exact); (0x4B400000<<23)==0 -> shift yields k<<23.
    int ib = __float_as_int(p) + (__float_as_int(t) << 23);
    return __int_as_float(ib);
}

// ---------------------------------------------------------------------------
// Kernel 1: per-row log-sum-exp over V=1024; one warp per (b,t,u) row.
// MUFU-pipe-bound (44 MUFU/warp x rt8 = 352 cyc/warp = the measured 23us) ->
// diet: 26 elements via MUFU EX2, 6 via the fma-pipe bit-trick exp2, and the
// butterfly uses ONE exp per step (only the smaller-max side needs scaling).
// All math in base-2 scaled domain; outputs stored base-2 (stride-66 blank).
// Rows outside [0,T_l) x [0,U_l] skipped.
// ---------------------------------------------------------------------------
__global__ void __launch_bounds__(256) lse_kernel(
    const float* __restrict__ logits,
    const int*   __restrict__ targets,
    const int*   __restrict__ logit_lengths,
    const int*   __restrict__ target_lengths)
{
    int warp = (int)((blockIdx.x * 256u + threadIdx.x) >> 5);
    int lane = threadIdx.x & 31;
    if (warp >= Bn * Tn * U1n) return;

    int b   = warp / (Tn * U1n);
    int rem = warp - b * (Tn * U1n);
    int t   = rem / U1n;
    int u   = rem - t * U1n;

    int Tl = logit_lengths[b];
    int Ul = target_lengths[b];
    if (t >= Tl || u > Ul) return;   // never read by the DP

    const float4* row = reinterpret_cast<const float4*>(logits) + (size_t)warp * (Vn / 4);
    float4 v[8];
#pragma unroll
    for (int j = 0; j < 8; j++) v[j] = row[j * 32 + lane];

    // Raw max (alu pipe).
    float m = v[0].x;
#pragma unroll
    for (int j = 0; j < 8; j++) {
        m = fmaxf(m, v[j].x); m = fmaxf(m, v[j].y);
        m = fmaxf(m, v[j].z); m = fmaxf(m, v[j].w);
    }

    // Scaled (base-2) domain: r_e = v_e*log2e - m*log2e, all <= ~0.
    float mS  = m * LOG2E;
    float nmS = -mS;

    float s = 0.0f;
#pragma unroll
    for (int j = 0; j < 6; j++) {        // 24 elements via MUFU
        s += ex2m(fmaf(v[j].x, LOG2E, nmS));
        s += ex2m(fmaf(v[j].y, LOG2E, nmS));
        s += ex2m(fmaf(v[j].z, LOG2E, nmS));
        s += ex2m(fmaf(v[j].w, LOG2E, nmS));
    }
    s += ex2m(fmaf(v[6].x, LOG2E, nmS)); // +2 MUFU = 26
    s += ex2m(fmaf(v[6].y, LOG2E, nmS));
    s += ex2p(fmaf(v[6].z, LOG2E, nmS)); // 6 via fma-pipe poly
    s += ex2p(fmaf(v[6].w, LOG2E, nmS));
    s += ex2p(fmaf(v[7].x, LOG2E, nmS));
    s += ex2p(fmaf(v[7].y, LOG2E, nmS));
    s += ex2p(fmaf(v[7].z, LOG2E, nmS));
    s += ex2p(fmaf(v[7].w, LOG2E, nmS));

    // blank class = V-1: lives in v[7].w of lane 31; grab before reduction.
    float blankv = __shfl_sync(0xffffffffu, v[7].w, 31);

    // Butterfly combine of (mS, s): one exp per step (scale the smaller side).
#pragma unroll
    for (int off = 16; off; off >>= 1) {
        float omS = __shfl_xor_sync(0xffffffffu, mS, off);
        float os  = __shfl_xor_sync(0xffffffffu, s,  off);
        float nm  = fmaxf(mS, omS);
        float dn  = fminf(mS, omS) - nm;       // <= 0
        float e   = ex2m(dn);
        float hi  = (mS >= omS) ? s  : os;
        float lo  = (mS >= omS) ? os : s;
        s  = fmaf(lo, e, hi);
        mS = nm;
    }
    float lse2 = mS + __log2f(s);              // base-2 LSE

    if (lane == 0) {
        g_blank[(b * Tn + t) * 66 + u] = fmaf(blankv, LOG2E, -lse2);
        if (u < Ul) {
            int tgt = targets[b * Un + u];
            g_emit[(b * Tn + t) * Un + u] =
                fmaf(logits[(size_t)warp * Vn + tgt], LOG2E, -lse2);
        }
    }
}

// ---------------------------------------------------------------------------
// Kernel 2: anti-diagonal wavefront DP, one warp per batch, base-2 log domain.
// (R15 version, validated at 17.7us.) Blocked ownership: lane l owns u=2l
// (slot0), u=2l+1 (slot1); u=64 = slot2 only when Ul==64. Lane0's missing
// left-neighbor handled by a dedicated -inf SMEM guard cell (stride-0 ptr).
// Boundary handling by construction (padded zero-filled SMEM, -inf regs).
// ---------------------------------------------------------------------------
#define PAD_LO   64
#define SROWS    256                    // rows -64..191
#define BLK_F    (SROWS * 66)           // 16896 floats
#define EMT_F    (SROWS * 64)           // 16384 floats
#define TAIL_F   68                     // pad for last prefetch + guard cell
#define TOT_F    (BLK_F + EMT_F + TAIL_F)
#define MINF_IDX (BLK_F + EMT_F + TAIL_F - 1)   // guard cell holding -inf

// Base-2 logaddexp: EX2 + degree-5 Estrin poly for log2(1+y), final FFMA fold.
// P(0)=0 keeps -inf algebra NaN-free (z clamped to -45 handles both--inf NaN).
__device__ __forceinline__ float lae2p(float va, float vb) {
    const float C1 =  1.4419672f;
    const float C2 = -0.7096747f;
    const float C3 =  0.4176170f;
    const float C4 = -0.1962970f;
    const float C5 =  0.0463940f;
    float mx = fmaxf(va, vb);
    float mn = fminf(va, vb);
    float z  = fmaxf(mn - mx, -45.0f);
    float y  = ex2m(z);
    float y2 = y * y;
    float t1 = fmaf(C2, y, C1);
    float t2 = fmaf(C4, y, C3);
    float t3 = fmaf(y2, t2, t1);
    float y4 = y2 * y2;
    float P  = fmaf(y4, C5, t3);
    return fmaf(y, P, mx);
}

template <bool S2>
__device__ __forceinline__ void dp_loop(
    const float* s_blank0, const float* s_emit0, const float* minf_cell,
    int lane, int d_end, float& rp0, float& rp1, float& rp2)
{
    const float NEG = neg_inf();
    const int u0 = 2 * lane;
    const int u1 = 2 * lane + 1;
    const bool l0 = (lane == 0);
    const int src = (lane + 31) & 31;

    // Incremental SMEM pointers, positioned for d = 1.
    const float* pb0 = s_blank0 + (0 - u0) * 66 + u0;           // blank row d-1-u0
    const float* pe0 = l0 ? minf_cell
                          : s_emit0 + (1 - u0) * 64 + (u0 - 1); // emit row d-u0, col u0-1
    const int    e0s = l0 ? 0 : 64;
    const float* pb1 = s_blank0 + (0 - u1) * 66 + u1;
    const float* pe1 = s_emit0  + (1 - u1) * 64 + (u1 - 1);
    const float* pb2 = s_blank0 + (0 - 64) * 66 + 64;
    const float* pe2 = s_emit0  + (1 - 64) * 64 + 63;

    // Diagonal d = 0: only cell (0,0) (lane0 slot0) = 0.
    float p0 = l0 ? 0.0f : NEG;
    float p1 = NEG, p2 = NEG;

    // Prologue prefetch: values for d = 1.
    float blk0 = *pb0; pb0 += 66;
    float emt0 = *pe0; pe0 += e0s;
    float blk1 = *pb1; pb1 += 66;
    float emt1 = *pe1; pe1 += 64;
    float blk2 = 0.f, emt2 = 0.f;
    if (S2) { blk2 = *pb2; pb2 += 66; emt2 = *pe2; pe2 += 64; }

#pragma unroll 2
    for (int d = 1; d <= d_end; d++) {
        float s1 = __shfl_sync(0xffffffffu, p1, src);

        // Prefetch diagonal d+1 (independent of this iteration's chain).
        float blk0n = *pb0; pb0 += 66;
        float emt0n = *pe0; pe0 += e0s;
        float blk1n = *pb1; pb1 += 66;
        float emt1n = *pe1; pe1 += 64;
        float blk2n = 0.f, emt2n = 0.f;
        if (S2) { blk2n = *pb2; pb2 += 66; emt2n = *pe2; pe2 += 64; }

        // lane0: emt0 = -inf cell -> s1 + emt0 = -inf (no select needed).
        float q0 = lae2p(p0 + blk0, s1 + emt0);
        float q1 = lae2p(p1 + blk1, p0 + emt1);   // left parent local (prev diag)
        float q2;
        if (S2) q2 = lae2p(p2 + blk2, p1 + emt2); // u=64 left = lane31 slot1

        p0 = q0; p1 = q1;
        if (S2) p2 = q2;

        blk0 = blk0n; emt0 = emt0n;
        blk1 = blk1n; emt1 = emt1n;
        if (S2) { blk2 = blk2n; emt2 = emt2n; }
    }

    rp0 = p0; rp1 = p1; rp2 = p2;
}

__global__ void __launch_bounds__(128) dp_kernel(
    const int* __restrict__ logit_lengths,
    const int* __restrict__ target_lengths,
    float*     __restrict__ out)
{
    int b    = blockIdx.x;
    int tid  = threadIdx.x;
    int lane = tid & 31;
    int Tl   = logit_lengths[b];
    int Ul   = target_lengths[b];

    extern __shared__ float sh[];
    float* s_blank0 = sh + PAD_LO * 66;              // row-0 of blank
    float* s_emit0  = sh + BLK_F + PAD_LO * 64;      // row-0 of emit

    // Zero the whole padded region (vectorized), then set the -inf guard cell.
    {
        float4* sh4 = reinterpret_cast<float4*>(sh);
        const float4 z4 = make_float4(0.f, 0.f, 0.f, 0.f);
        for (int i = tid; i < TOT_F / 4; i += 128) sh4[i] = z4;
    }
    __syncthreads();

    // Flat vectorized preload (layouts match exactly: stride 66 / 64).
    {
        const float2* gb2 = reinterpret_cast<const float2*>(g_blank + b * Tn * 66);
        float2* sb2 = reinterpret_cast<float2*>(s_blank0);
        int n2 = Tl * 33;
        for (int i = tid; i < n2; i += 128) sb2[i] = gb2[i];

        const float4* ge4 = reinterpret_cast<const float4*>(g_emit + b * Tn * Un);
        float4* se4 = reinterpret_cast<float4*>(s_emit0);
        int n4 = Tl * 16;
        for (int i = tid; i < n4; i += 128) se4[i] = ge4[i];

        if (tid == 0) sh[MINF_IDX] = neg_inf();
    }
    __syncthreads();
    if (tid >= 32) return;               // warp 0 runs the DP alone

    const int t_last = Tl - 1;
    const int u_last = Ul;
    const int d_end  = t_last + u_last;

    float p0, p1, p2;
    float af;
    if (u_last == 64) {
        dp_loop<true >(s_blank0, s_emit0, sh + MINF_IDX, lane, d_end, p0, p1, p2);
        af = __shfl_sync(0xffffffffu, p2, 31);
    } else {
        dp_loop<false>(s_blank0, s_emit0, sh + MINF_IDX, lane, d_end, p0, p1, p2);
        if (u_last & 1) af = __shfl_sync(0xffffffffu, p1, u_last >> 1);
        else            af = __shfl_sync(0xffffffffu, p0, u_last >> 1);
    }

    if (lane == 0) {
        out[b] = -(af + s_blank0[t_last * 66 + u_last]) * LN2;
    }
}

// ---------------------------------------------------------------------------
extern "C" void kernel_launch(void* const* d_in, const int* in_sizes, int n_in,
                              void* d_out, int out_size)
{
    const float* logits         = (const float*)d_in[0];
    const int*   targets        = (const int*)  d_in[1];
    const int*   logit_lengths  = (const int*)  d_in[2];
    const int*   target_lengths = (const int*)  d_in[3];
    float*       out            = (float*)      d_out;

    const int smem_bytes = TOT_F * (int)sizeof(float);
    static int attr_set = 0;
    if (!attr_set) {
        cudaFuncSetAttribute(dp_kernel, cudaFuncAttributeMaxDynamicSharedMemorySize, smem_bytes);
        attr_set = 1;
    }

    int rows   = Bn * Tn * U1n;            // 66560 rows -> one warp each
    int blocks = (rows * 32 + 255) / 256;  // 8320 blocks

    lse_kernel<<<blocks, 256>>>(logits, targets, logit_lengths, target_lengths);
    dp_kernel<<<Bn, 128, smem_bytes>>>(logit_lengths, target_lengths, out);
}